// round 16
// baseline (speedup 1.0000x reference)
#include <cuda_runtime.h>
#include <cuda_fp16.h>
#include <cstdint>

#define BB 2
#define SS 1024
#define DD 1024
#define HH 16
#define DKK 64
#define FF_ 4096
#define LL 6

// ---------------- scratch (__device__ globals: allocation-free) --------------
__device__ float g_x [BB*SS*DD];
__device__ __half g_p [2*BB*SS*DD];   // split-K partials (fp16, 8 MB)

#define WL_CHUNK (4*DD*DD + DD*FF_ + FF_*DD)
#define W_TOTAL  (LL * WL_CHUNK)
#define OFF_Q 0
#define OFF_K (DD*DD)
#define OFF_V (2*DD*DD)
#define OFF_O (3*DD*DD)
#define OFF_1 (4*DD*DD)
#define OFF_2 (4*DD*DD + DD*FF_)
__device__ __half g_w [W_TOTAL];

__device__ __half g_a [BB*SS*DD];
__device__ __half g_f [BB*SS*FF_];
__device__ __half g_q [BB*SS*DD];
__device__ __half g_k [BB*SS*DD];
__device__ __half g_v [BB*SS*DD];

// ---------------- PTX helpers -------------------------------------------------
__device__ __forceinline__ uint32_t smem_u32(const void* p) {
    uint32_t a;
    asm("{ .reg .u64 t; cvta.to.shared.u64 t, %1; cvt.u32.u64 %0, t; }" : "=r"(a) : "l"(p));
    return a;
}
#define CP16(d, s) asm volatile("cp.async.cg.shared.global [%0], [%1], 16;" :: "r"(d), "l"(s))
#define CP_COMMIT() asm volatile("cp.async.commit_group;" ::: "memory")

#define LDSM4(r, addr) \
    asm volatile("ldmatrix.sync.aligned.m8n8.x4.shared.b16 {%0,%1,%2,%3}, [%4];" \
        : "=r"((r)[0]), "=r"((r)[1]), "=r"((r)[2]), "=r"((r)[3]) : "r"(addr))
#define LDSM4T(r, addr) \
    asm volatile("ldmatrix.sync.aligned.m8n8.x4.trans.shared.b16 {%0,%1,%2,%3}, [%4];" \
        : "=r"((r)[0]), "=r"((r)[1]), "=r"((r)[2]), "=r"((r)[3]) : "r"(addr))

#define MMAF16(d, a, b) \
    asm volatile("mma.sync.aligned.m16n8k16.row.col.f32.f16.f16.f32 " \
        "{%0,%1,%2,%3}, {%4,%5,%6,%7}, {%8,%9}, {%0,%1,%2,%3};" \
        : "+f"((d)[0]), "+f"((d)[1]), "+f"((d)[2]), "+f"((d)[3]) \
        : "r"((a)[0]), "r"((a)[1]), "r"((a)[2]), "r"((a)[3]), "r"((b)[0]), "r"((b)[1]))

__device__ __forceinline__ uint32_t h2pack(float a, float b) {
    __half2 h = __floats2half2_rn(a, b);
    return *(uint32_t*)&h;
}

// ---------------- block reduce -------------------------------------------------
__device__ __forceinline__ float blockReduceSum(float v) {
    __shared__ float sh[8];
    __shared__ float res;
    int lane = threadIdx.x & 31, w = threadIdx.x >> 5;
#pragma unroll
    for (int o = 16; o; o >>= 1) v += __shfl_xor_sync(0xffffffffu, v, o);
    __syncthreads();
    if (lane == 0) sh[w] = v;
    __syncthreads();
    if (threadIdx.x == 0) {
        float s = 0.f;
#pragma unroll
        for (int i = 0; i < 8; i++) s += sh[i];
        res = s;
    }
    __syncthreads();
    return res;
}

// ---------------- embed --------------------------------------------------------
__global__ void __launch_bounds__(256) embed_kernel(
    const int* __restrict__ ids, const float* __restrict__ emb,
    const float* __restrict__ pe, float* __restrict__ x)
{
    int row = blockIdx.x;
    int col = threadIdx.x * 4;
    int id  = ids[row];
    int s   = row & (SS - 1);
    float4 e = *(const float4*)&emb[(size_t)id * DD + col];
    float4 p = *(const float4*)&pe [(size_t)s  * DD + col];
    float4 o;
    o.x = e.x * 32.0f + p.x;
    o.y = e.y * 32.0f + p.y;
    o.z = e.z * 32.0f + p.z;
    o.w = e.w * 32.0f + p.w;
    *(float4*)&x[(size_t)row * DD + col] = o;
}

// ---------------- LayerNorm: fp16 out (plain; layer-0 LN1) -----------------------
__global__ void __launch_bounds__(256) ln_h_kernel(
    const float* __restrict__ x, const float* __restrict__ g,
    const float* __restrict__ b, __half* __restrict__ oh)
{
    int row = blockIdx.x;
    int col = threadIdx.x * 4;
    float4 v = *(const float4*)&x[(size_t)row * DD + col];
    float mean = blockReduceSum(v.x + v.y + v.z + v.w) * (1.0f / DD);
    float dx = v.x - mean, dy = v.y - mean, dz = v.z - mean, dw = v.w - mean;
    float var = blockReduceSum(dx*dx + dy*dy + dz*dz + dw*dw) * (1.0f / DD);
    float rstd = rsqrtf(var + 1e-6f);
    float4 gg = *(const float4*)&g[col];
    float4 bb = *(const float4*)&b[col];
    float ox = dx * rstd * gg.x + bb.x;
    float oy = dy * rstd * gg.y + bb.y;
    float oz = dz * rstd * gg.z + bb.z;
    float ow = dw * rstd * gg.w + bb.w;
    uint2 H = make_uint2(h2pack(ox, oy), h2pack(oz, ow));
    ((uint2*)oh)[((size_t)row * DD + col) >> 2] = H;
}

// ---------------- fused: x += p0+p1+bias; LN(x) -> fp16 oh -----------------------
__global__ void __launch_bounds__(256) ln_h_red_kernel(
    float* __restrict__ x, const __half* __restrict__ p,
    const float* __restrict__ bias,
    const float* __restrict__ g, const float* __restrict__ b,
    __half* __restrict__ oh)
{
    int row = blockIdx.x;
    int col = threadIdx.x * 4;
    size_t i = (size_t)row * DD + col;
    float4 v  = *(float4*)&x[i];
    uint2 p0u = *(const uint2*)&p[i];
    uint2 p1u = *(const uint2*)&p[i + (size_t)BB*SS*DD];
    float2 q0a = __half22float2(*(__half2*)&p0u.x);
    float2 q0b = __half22float2(*(__half2*)&p0u.y);
    float2 q1a = __half22float2(*(__half2*)&p1u.x);
    float2 q1b = __half22float2(*(__half2*)&p1u.y);
    float4 bi = *(const float4*)&bias[col];
    v.x += q0a.x + q1a.x + bi.x;
    v.y += q0a.y + q1a.y + bi.y;
    v.z += q0b.x + q1b.x + bi.z;
    v.w += q0b.y + q1b.y + bi.w;
    *(float4*)&x[i] = v;
    float mean = blockReduceSum(v.x + v.y + v.z + v.w) * (1.0f / DD);
    float dx = v.x - mean, dy = v.y - mean, dz = v.z - mean, dw = v.w - mean;
    float var = blockReduceSum(dx*dx + dy*dy + dz*dz + dw*dw) * (1.0f / DD);
    float rstd = rsqrtf(var + 1e-6f);
    float4 gg = *(const float4*)&g[col];
    float4 bb = *(const float4*)&b[col];
    float ox = dx * rstd * gg.x + bb.x;
    float oy = dy * rstd * gg.y + bb.y;
    float oz = dz * rstd * gg.z + bb.z;
    float ow = dw * rstd * gg.w + bb.w;
    uint2 H = make_uint2(h2pack(ox, oy), h2pack(oz, ow));
    ((uint2*)oh)[i >> 2] = H;
}

// ---------------- fused final: xn = x+p0+p1+bias; LN(xn) -> fp32 out -------------
__global__ void __launch_bounds__(256) ln_red_final_kernel(
    const float* __restrict__ x, const __half* __restrict__ p,
    const float* __restrict__ bias,
    const float* __restrict__ g, const float* __restrict__ b,
    float* __restrict__ out)
{
    int row = blockIdx.x;
    int col = threadIdx.x * 4;
    size_t i = (size_t)row * DD + col;
    float4 v  = *(const float4*)&x[i];
    uint2 p0u = *(const uint2*)&p[i];
    uint2 p1u = *(const uint2*)&p[i + (size_t)BB*SS*DD];
    float2 q0a = __half22float2(*(__half2*)&p0u.x);
    float2 q0b = __half22float2(*(__half2*)&p0u.y);
    float2 q1a = __half22float2(*(__half2*)&p1u.x);
    float2 q1b = __half22float2(*(__half2*)&p1u.y);
    float4 bi = *(const float4*)&bias[col];
    v.x += q0a.x + q1a.x + bi.x;
    v.y += q0a.y + q1a.y + bi.y;
    v.z += q0b.x + q1b.x + bi.z;
    v.w += q0b.y + q1b.y + bi.w;
    float mean = blockReduceSum(v.x + v.y + v.z + v.w) * (1.0f / DD);
    float dx = v.x - mean, dy = v.y - mean, dz = v.z - mean, dw = v.w - mean;
    float var = blockReduceSum(dx*dx + dy*dy + dz*dz + dw*dw) * (1.0f / DD);
    float rstd = rsqrtf(var + 1e-6f);
    float4 gg = *(const float4*)&g[col];
    float4 bb = *(const float4*)&b[col];
    float4 o;
    o.x = dx * rstd * gg.x + bb.x;
    o.y = dy * rstd * gg.y + bb.y;
    o.z = dz * rstd * gg.z + bb.z;
    o.w = dw * rstd * gg.w + bb.w;
    *(float4*)&out[i] = o;
}

// ---------------- batched weight prep (fp32 [K,N] -> fp16 [N,K]) ------------------
__global__ void __launch_bounds__(256) prep_qkvo(
    const float* __restrict__ wq, const float* __restrict__ wk,
    const float* __restrict__ wv, const float* __restrict__ wo,
    __half* __restrict__ dh)
{
    __shared__ float tile[32][33];
    int z = blockIdx.z, l = z >> 2, ws = z & 3;
    const float* src = (ws == 0 ? wq : ws == 1 ? wk : ws == 2 ? wv : wo) + (size_t)l * DD * DD;
    size_t dbase = (size_t)l * WL_CHUNK + (size_t)ws * DD * DD;
    int k0 = blockIdx.y * 32, n0 = blockIdx.x * 32;
    int tx = threadIdx.x & 31, ty = threadIdx.x >> 5;
#pragma unroll
    for (int i = ty; i < 32; i += 8)
        tile[i][tx] = src[(size_t)(k0 + i) * DD + n0 + tx];
    __syncthreads();
#pragma unroll
    for (int i = ty; i < 32; i += 8)
        dh[dbase + (size_t)(n0 + i) * DD + k0 + tx] = __float2half_rn(tile[tx][i]);
}

__global__ void __launch_bounds__(256) prep_ff(
    const float* __restrict__ src, __half* __restrict__ dh,
    int dstOff, int K, int N)
{
    __shared__ float tile[32][33];
    int l = blockIdx.z;
    const float* s = src + (size_t)l * K * N;
    size_t dbase = (size_t)l * WL_CHUNK + dstOff;
    int k0 = blockIdx.y * 32, n0 = blockIdx.x * 32;
    int tx = threadIdx.x & 31, ty = threadIdx.x >> 5;
#pragma unroll
    for (int i = ty; i < 32; i += 8)
        tile[i][tx] = s[(size_t)(k0 + i) * N + n0 + tx];
    __syncthreads();
#pragma unroll
    for (int i = ty; i < 32; i += 8)
        dh[dbase + (size_t)(n0 + i) * K + k0 + tx] = __float2half_rn(tile[tx][i]);
}

// ================================================================================
// fp16 GEMM (R8 config): 256 thr, 128x128 tile, 32x64 warp tiles, 2 CTAs/SM.
// EP: 4 = fp16 out, 5 = relu(+bias) fp16 out.
// ================================================================================
struct BPtr { const __half* h; float* c; __half* ch; };

#define STAGE_BYTES 36864
#define MM_SMEM (2 * STAGE_BYTES)

template<int EP>
__global__ void __launch_bounds__(256, 2) mmagemm(
    const __half* __restrict__ Ah,
    BPtr p0, BPtr p1, BPtr p2,
    const float* __restrict__ bias, const float* __restrict__ Rs,
    int M, int N, int K)
{
    extern __shared__ char smem[];
    uint32_t sb = smem_u32(smem);
    int z = blockIdx.z;
    BPtr P = (z == 0) ? p0 : (z == 1 ? p1 : p2);
    const __half* Bh = P.h;

    int tid = threadIdx.x;
    int bm = blockIdx.y * 128, bn = blockIdx.x * 128;

    const __half* Ab = Ah + (size_t)bm * K;
    const __half* Bb = Bh + (size_t)bn * K;

    auto load_stage = [&](int s, int k0) {
        uint32_t st = sb + (uint32_t)s * STAGE_BYTES;
#pragma unroll
        for (int i = 0; i < 4; i++) {
            int id = i * 256 + tid;
            int r = id >> 3, c = id & 7;
            uint32_t so = (uint32_t)(r * 144 + c * 16);
            size_t go = (size_t)r * K + k0 + c * 8;
            CP16(st +         so, (const char*)(Ab + go));
            CP16(st + 18432 + so, (const char*)(Bb + go));
        }
    };

    int wid = tid >> 5, lane = tid & 31;
    int wm = (wid & 3) * 32;
    int wn = (wid >> 2) * 64;
    int lrow  = lane & 15;
    int lcol8 = (lane >> 4) * 8;

    float acc[2][8][4];
#pragma unroll
    for (int a = 0; a < 2; a++)
#pragma unroll
        for (int b = 0; b < 8; b++)
#pragma unroll
            for (int cth = 0; cth < 4; cth++) acc[a][b][cth] = 0.f;

    int NT = K >> 6;
    load_stage(0, 0);
    CP_COMMIT();

    for (int t = 0; t < NT; t++) {
        if (t + 1 < NT) {
            load_stage((t + 1) & 1, (t + 1) * 64);
            CP_COMMIT();
            asm volatile("cp.async.wait_group 1;" ::: "memory");
        } else {
            asm volatile("cp.async.wait_group 0;" ::: "memory");
        }
        __syncthreads();

        uint32_t sA = sb + (uint32_t)(t & 1) * STAGE_BYTES;
        uint32_t sB = sA + 18432;
#pragma unroll
        for (int ks = 0; ks < 4; ks++) {
            int k0 = ks * 16;
            uint32_t ah[2][4];
#pragma unroll
            for (int mf = 0; mf < 2; mf++) {
                uint32_t ad = sA + (uint32_t)((wm + mf * 16 + lrow) * 144 + (k0 + lcol8) * 2);
                LDSM4(ah[mf], ad);
            }
#pragma unroll
            for (int nf2 = 0; nf2 < 4; nf2++) {
                uint32_t ad = sB + (uint32_t)((wn + nf2 * 16 + lrow) * 144 + (k0 + lcol8) * 2);
                uint32_t tmp[4];
                LDSM4(tmp, ad);
                uint32_t b0[2] = { tmp[0], tmp[2] };
                uint32_t b1[2] = { tmp[1], tmp[3] };
#pragma unroll
                for (int mf = 0; mf < 2; mf++) {
                    MMAF16(acc[mf][nf2*2],   ah[mf], b0);
                    MMAF16(acc[mf][nf2*2+1], ah[mf], b1);
                }
            }
        }
        __syncthreads();
    }

#pragma unroll
    for (int mf = 0; mf < 2; mf++) {
        int r0 = bm + wm + mf * 16 + (lane >> 2);
#pragma unroll
        for (int nf = 0; nf < 8; nf++) {
            int col = bn + wn + nf * 8 + (lane & 3) * 2;
            float2 v0 = make_float2(acc[mf][nf][0], acc[mf][nf][1]);
            float2 v1 = make_float2(acc[mf][nf][2], acc[mf][nf][3]);
            if (EP == 5) {
                float2 bi = *(const float2*)&bias[col];
                v0.x = fmaxf(v0.x + bi.x, 0.f); v0.y = fmaxf(v0.y + bi.y, 0.f);
                v1.x = fmaxf(v1.x + bi.x, 0.f); v1.y = fmaxf(v1.y + bi.y, 0.f);
            }
            *(uint32_t*)&P.ch[(size_t)r0 * N + col]       = h2pack(v0.x, v0.y);
            *(uint32_t*)&P.ch[(size_t)(r0 + 8) * N + col] = h2pack(v1.x, v1.y);
        }
    }
}

// ================================================================================
// Split-K GEMM: fp16 partials, z = K-split index (K/2 each). (Wo and FF2)
// ================================================================================
__global__ void __launch_bounds__(256, 2) mmagemm_sk(
    const __half* __restrict__ Ah, const __half* __restrict__ Bh,
    __half* __restrict__ Part, int M, int N, int K)
{
    extern __shared__ char smem[];
    uint32_t sb = smem_u32(smem);
    int z = blockIdx.z;
    int kOff = z * (K >> 1);
    int kLen = K >> 1;
    __half* C = Part + (size_t)z * M * N;

    int tid = threadIdx.x;
    int bm = blockIdx.y * 128, bn = blockIdx.x * 128;

    const __half* Ab = Ah + (size_t)bm * K + kOff;
    const __half* Bb = Bh + (size_t)bn * K + kOff;

    auto load_stage = [&](int s, int k0) {
        uint32_t st = sb + (uint32_t)s * STAGE_BYTES;
#pragma unroll
        for (int i = 0; i < 4; i++) {
            int id = i * 256 + tid;
            int r = id >> 3, c = id & 7;
            uint32_t so = (uint32_t)(r * 144 + c * 16);
            size_t go = (size_t)r * K + k0 + c * 8;
            CP16(st +         so, (const char*)(Ab + go));
            CP16(st + 18432 + so, (const char*)(Bb + go));
        }
    };

    int wid = tid >> 5, lane = tid & 31;
    int wm = (wid & 3) * 32;
    int wn = (wid >> 2) * 64;
    int lrow  = lane & 15;
    int lcol8 = (lane >> 4) * 8;

    float acc[2][8][4];
#pragma unroll
    for (int a = 0; a < 2; a++)
#pragma unroll
        for (int b = 0; b < 8; b++)
#pragma unroll
            for (int cth = 0; cth < 4; cth++) acc[a][b][cth] = 0.f;

    int NT = kLen >> 6;
    load_stage(0, 0);
    CP_COMMIT();

    for (int t = 0; t < NT; t++) {
        if (t + 1 < NT) {
            load_stage((t + 1) & 1, (t + 1) * 64);
            CP_COMMIT();
            asm volatile("cp.async.wait_group 1;" ::: "memory");
        } else {
            asm volatile("cp.async.wait_group 0;" ::: "memory");
        }
        __syncthreads();

        uint32_t sA = sb + (uint32_t)(t & 1) * STAGE_BYTES;
        uint32_t sB = sA + 18432;
#pragma unroll
        for (int ks = 0; ks < 4; ks++) {
            int k0 = ks * 16;
            uint32_t ah[2][4];
#pragma unroll
            for (int mf = 0; mf < 2; mf++) {
                uint32_t ad = sA + (uint32_t)((wm + mf * 16 + lrow) * 144 + (k0 + lcol8) * 2);
                LDSM4(ah[mf], ad);
            }
#pragma unroll
            for (int nf2 = 0; nf2 < 4; nf2++) {
                uint32_t ad = sB + (uint32_t)((wn + nf2 * 16 + lrow) * 144 + (k0 + lcol8) * 2);
                uint32_t tmp[4];
                LDSM4(tmp, ad);
                uint32_t b0[2] = { tmp[0], tmp[2] };
                uint32_t b1[2] = { tmp[1], tmp[3] };
#pragma unroll
                for (int mf = 0; mf < 2; mf++) {
                    MMAF16(acc[mf][nf2*2],   ah[mf], b0);
                    MMAF16(acc[mf][nf2*2+1], ah[mf], b1);
                }
            }
        }
        __syncthreads();
    }

#pragma unroll
    for (int mf = 0; mf < 2; mf++) {
        int r0 = bm + wm + mf * 16 + (lane >> 2);
#pragma unroll
        for (int nf = 0; nf < 8; nf++) {
            int col = bn + wn + nf * 8 + (lane & 3) * 2;
            *(uint32_t*)&C[(size_t)r0 * N + col]       = h2pack(acc[mf][nf][0], acc[mf][nf][1]);
            *(uint32_t*)&C[(size_t)(r0 + 8) * N + col] = h2pack(acc[mf][nf][2], acc[mf][nf][3]);
        }
    }
}

// ================================================================================
// Flash attention: fp16 Q/K/V, fp32 accum, online softmax. 2 CTAs/SM. (unchanged)
// ================================================================================
#define FA_STRIDE 144
#define FA_Q 0
#define FA_KV0 18432
#define FA_KVSTAGE 36864
#define FA_MB 92160
#define FA_SMEM 93184

__global__ void __launch_bounds__(256, 2) flash_kernel(
    const __half* __restrict__ q, const __half* __restrict__ k,
    const __half* __restrict__ v,
    const float* __restrict__ am,
    __half* __restrict__ o)
{
    extern __shared__ char smem[];
    uint32_t sb = smem_u32(smem);
    float* maskf = (float*)(smem + FA_MB);

    int qt = blockIdx.x;
    int bh = blockIdx.y;
    int b  = bh >> 4, hd = bh & 15;
    int tid = threadIdx.x;
    int wid = tid >> 5, lane = tid & 31;
    int wm = wid * 16;
    int lrow  = lane & 15;
    int lcol8 = (lane >> 4) * 8;

    size_t qrow0 = (size_t)b * SS + qt * 128;
    size_t hoff  = (size_t)hd * DKK;

#pragma unroll
    for (int i = 0; i < 4; i++) {
        int id = i * 256 + tid;
        int r = id >> 3, c = id & 7;
        uint32_t so = (uint32_t)(r * FA_STRIDE + c * 16);
        size_t gq = (qrow0 + r) * DD + hoff + c * 8;
        CP16(sb + FA_Q + so, (const char*)(q + gq));
        size_t gk = ((size_t)b * SS + r) * DD + hoff + c * 8;
        CP16(sb + FA_KV0 +         so, (const char*)(k + gk));
        CP16(sb + FA_KV0 + 18432 + so, (const char*)(v + gk));
    }
    CP_COMMIT();
    if (tid < 128) {
        float m = am[(size_t)b * SS + tid];
        maskf[tid] = (m == 0.f) ? -1e9f : 0.f;
    }

    float m0 = -1e30f, m1 = -1e30f, s0 = 0.f, s1 = 0.f;
    float oacc[8][4];
#pragma unroll
    for (int i = 0; i < 8; i++)
#pragma unroll
        for (int j = 0; j < 4; j++) oacc[i][j] = 0.f;

    for (int t = 0; t < 8; t++) {
        asm volatile("cp.async.wait_group 0;" ::: "memory");
        __syncthreads();

        if (t + 1 < 8) {
            uint32_t kvn = sb + FA_KV0 + (uint32_t)((t + 1) & 1) * FA_KVSTAGE;
#pragma unroll
            for (int i = 0; i < 4; i++) {
                int id = i * 256 + tid;
                int r = id >> 3, c = id & 7;
                uint32_t so = (uint32_t)(r * FA_STRIDE + c * 16);
                size_t go = ((size_t)b * SS + (t + 1) * 128 + r) * DD + hoff + c * 8;
                CP16(kvn +         so, (const char*)(k + go));
                CP16(kvn + 18432 + so, (const char*)(v + go));
            }
            CP_COMMIT();
            if (tid < 128) {
                float m = am[(size_t)b * SS + (t + 1) * 128 + tid];
                maskf[((t + 1) & 1) * 128 + tid] = (m == 0.f) ? -1e9f : 0.f;
            }
        }

        uint32_t kvb = sb + FA_KV0 + (uint32_t)(t & 1) * FA_KVSTAGE;
        const float* mk = maskf + (t & 1) * 128;

        float sacc[16][4];
#pragma unroll
        for (int i = 0; i < 16; i++)
#pragma unroll
            for (int j = 0; j < 4; j++) sacc[i][j] = 0.f;

#pragma unroll
        for (int kf = 0; kf < 4; kf++) {
            uint32_t aq[4];
            uint32_t ad = sb + FA_Q + (uint32_t)((wm + lrow) * FA_STRIDE + (kf * 16 + lcol8) * 2);
            LDSM4(aq, ad);
#pragma unroll
            for (int nf2 = 0; nf2 < 8; nf2++) {
                uint32_t kd = kvb + (uint32_t)((nf2 * 16 + lrow) * FA_STRIDE + (kf * 16 + lcol8) * 2);
                uint32_t tmp[4];
                LDSM4(tmp, kd);
                uint32_t b0[2] = { tmp[0], tmp[2] };
                uint32_t b1[2] = { tmp[1], tmp[3] };
                MMAF16(sacc[nf2*2],   aq, b0);
                MMAF16(sacc[nf2*2+1], aq, b1);
            }
        }

        float mn0 = m0, mn1 = m1;
#pragma unroll
        for (int nf = 0; nf < 16; nf++) {
            int col = nf * 8 + (lane & 3) * 2;
            float b0 = mk[col], b1 = mk[col + 1];
            sacc[nf][0] = sacc[nf][0] * 0.125f + b0;
            sacc[nf][1] = sacc[nf][1] * 0.125f + b1;
            sacc[nf][2] = sacc[nf][2] * 0.125f + b0;
            sacc[nf][3] = sacc[nf][3] * 0.125f + b1;
            mn0 = fmaxf(mn0, fmaxf(sacc[nf][0], sacc[nf][1]));
            mn1 = fmaxf(mn1, fmaxf(sacc[nf][2], sacc[nf][3]));
        }
        mn0 = fmaxf(mn0, __shfl_xor_sync(0xffffffffu, mn0, 1));
        mn0 = fmaxf(mn0, __shfl_xor_sync(0xffffffffu, mn0, 2));
        mn1 = fmaxf(mn1, __shfl_xor_sync(0xffffffffu, mn1, 1));
        mn1 = fmaxf(mn1, __shfl_xor_sync(0xffffffffu, mn1, 2));
        float alpha0 = __expf(m0 - mn0);
        float alpha1 = __expf(m1 - mn1);
        m0 = mn0; m1 = mn1;
        float rs0 = 0.f, rs1 = 0.f;
#pragma unroll
        for (int nf = 0; nf < 16; nf++) {
            sacc[nf][0] = __expf(sacc[nf][0] - mn0);
            sacc[nf][1] = __expf(sacc[nf][1] - mn0);
            sacc[nf][2] = __expf(sacc[nf][2] - mn1);
            sacc[nf][3] = __expf(sacc[nf][3] - mn1);
            rs0 += sacc[nf][0] + sacc[nf][1];
            rs1 += sacc[nf][2] + sacc[nf][3];
        }
        rs0 += __shfl_xor_sync(0xffffffffu, rs0, 1);
        rs0 += __shfl_xor_sync(0xffffffffu, rs0, 2);
        rs1 += __shfl_xor_sync(0xffffffffu, rs1, 1);
        rs1 += __shfl_xor_sync(0xffffffffu, rs1, 2);
        s0 = s0 * alpha0 + rs0;
        s1 = s1 * alpha1 + rs1;
#pragma unroll
        for (int i = 0; i < 8; i++) {
            oacc[i][0] *= alpha0; oacc[i][1] *= alpha0;
            oacc[i][2] *= alpha1; oacc[i][3] *= alpha1;
        }

#pragma unroll
        for (int kk = 0; kk < 8; kk++) {
            uint32_t ap[4];
            ap[0] = h2pack(sacc[2*kk][0],   sacc[2*kk][1]);
            ap[1] = h2pack(sacc[2*kk][2],   sacc[2*kk][3]);
            ap[2] = h2pack(sacc[2*kk+1][0], sacc[2*kk+1][1]);
            ap[3] = h2pack(sacc[2*kk+1][2], sacc[2*kk+1][3]);
#pragma unroll
            for (int dv2 = 0; dv2 < 4; dv2++) {
                uint32_t tmp[4];
                uint32_t vd = kvb + 18432 + (uint32_t)((kk * 16 + lrow) * FA_STRIDE + (dv2 * 16 + lcol8) * 2);
                LDSM4T(tmp, vd);
                uint32_t bv0[2] = { tmp[0], tmp[1] };
                uint32_t bv1[2] = { tmp[2], tmp[3] };
                MMAF16(oacc[dv2*2],   ap, bv0);
                MMAF16(oacc[dv2*2+1], ap, bv1);
            }
        }
    }

    float inv0 = 1.0f / s0, inv1 = 1.0f / s1;
    int r0 = (int)qrow0 + wm + (lane >> 2);
#pragma unroll
    for (int nf = 0; nf < 8; nf++) {
        int col = (int)hoff + nf * 8 + (lane & 3) * 2;
        *(uint32_t*)&o[(size_t)r0 * DD + col]       = h2pack(oacc[nf][0] * inv0, oacc[nf][1] * inv0);
        *(uint32_t*)&o[(size_t)(r0 + 8) * DD + col] = h2pack(oacc[nf][2] * inv1, oacc[nf][3] * inv1);
    }
}

// ---------------- host orchestration ---------------------------------------------
extern "C" void kernel_launch(void* const* d_in, const int* in_sizes, int n_in,
                              void* d_out, int out_size)
{
    const int*   ids  = (const int*)  d_in[0];
    const float* am   = (const float*)d_in[1];
    const float* emb  = (const float*)d_in[2];
    const float* pe   = (const float*)d_in[3];
    const float* wq   = (const float*)d_in[4];
    const float* wk   = (const float*)d_in[5];
    const float* wv   = (const float*)d_in[6];
    const float* wo   = (const float*)d_in[7];
    const float* bo   = (const float*)d_in[8];
    const float* w1   = (const float*)d_in[9];
    const float* b1   = (const float*)d_in[10];
    const float* w2   = (const float*)d_in[11];
    const float* b2   = (const float*)d_in[12];
    const float* ln1s = (const float*)d_in[13];
    const float* ln1b = (const float*)d_in[14];
    const float* ln2s = (const float*)d_in[15];
    const float* ln2b = (const float*)d_in[16];
    const float* lnfs = (const float*)d_in[17];
    const float* lnfb = (const float*)d_in[18];
    float* out = (float*)d_out;

    float *x;
    __half *part, *w, *a, *f, *q_, *k_, *v_;
    cudaGetSymbolAddress((void**)&x,    g_x);
    cudaGetSymbolAddress((void**)&part, g_p);
    cudaGetSymbolAddress((void**)&w,    g_w);
    cudaGetSymbolAddress((void**)&a,    g_a);
    cudaGetSymbolAddress((void**)&f,    g_f);
    cudaGetSymbolAddress((void**)&q_,   g_q);
    cudaGetSymbolAddress((void**)&k_,   g_k);
    cudaGetSymbolAddress((void**)&v_,   g_v);

    cudaFuncSetAttribute((const void*)mmagemm<4>, cudaFuncAttributeMaxDynamicSharedMemorySize, MM_SMEM);
    cudaFuncSetAttribute((const void*)mmagemm<5>, cudaFuncAttributeMaxDynamicSharedMemorySize, MM_SMEM);
    cudaFuncSetAttribute((const void*)mmagemm_sk, cudaFuncAttributeMaxDynamicSharedMemorySize, MM_SMEM);
    cudaFuncSetAttribute((const void*)flash_kernel, cudaFuncAttributeMaxDynamicSharedMemorySize, FA_SMEM);

    const int M = BB * SS;

    embed_kernel<<<M, 256>>>(ids, emb, pe, x);
    prep_qkvo<<<dim3(DD/32, DD/32, 4*LL), 256>>>(wq, wk, wv, wo, w);

    // layer-0 LN1 (x from embed)
    ln_h_kernel<<<M, 256>>>(x, ln1s, ln1b, a);

    for (int l = 0; l < LL; l++) {
        size_t lb = (size_t)l * WL_CHUNK;

        // fused Q,K,V projections (a = LN1 out)
        BPtr pq = { w + lb + OFF_Q, nullptr, q_ };
        BPtr pk = { w + lb + OFF_K, nullptr, k_ };
        BPtr pv = { w + lb + OFF_V, nullptr, v_ };
        mmagemm<4><<<dim3(DD/128, M/128, 3), 256, MM_SMEM>>>(a, pq, pk, pv,
                                                             nullptr, nullptr, M, DD, DD);

        if (l == 0) {
            prep_ff<<<dim3(FF_/32, DD/32, LL), 256>>>(w1, w, OFF_1, DD, FF_);
            prep_ff<<<dim3(DD/32, FF_/32, LL), 256>>>(w2, w, OFF_2, FF_, DD);
        }

        // flash attention -> fp16 attn out in a
        flash_kernel<<<dim3(SS/128, BB*HH), 256, FA_SMEM>>>(q_, k_, v_, am, a);

        // Wo: split-K=2 -> fp16 partials; fused reduce+LN2 -> a  (x updated in place)
        mmagemm_sk<<<dim3(DD/128, M/128, 2), 256, MM_SMEM>>>(a, w + lb + OFF_O, part,
                                                             M, DD, DD);
        ln_h_red_kernel<<<M, 256>>>(x, part, bo + l*DD, ln2s + l*DD, ln2b + l*DD, a);

        // ff = relu(a @ W1 + b1) -> f
        BPtr p1 = { w + lb + OFF_1, nullptr, f };
        mmagemm<5><<<dim3(FF_/128, M/128, 1), 256, MM_SMEM>>>(a, p1, p1, p1,
                                                              b1 + l*FF_, nullptr, M, FF_, DD);

        // FF2: split-K=2 -> fp16 partials; fused reduce + (next LN1 | final LN)
        mmagemm_sk<<<dim3(DD/128, M/128, 2), 256, MM_SMEM>>>(f, w + lb + OFF_2, part,
                                                             M, DD, FF_);
        if (l + 1 < LL) {
            ln_h_red_kernel<<<M, 256>>>(x, part, b2 + l*DD,
                                        ln1s + (l+1)*DD, ln1b + (l+1)*DD, a);
        } else {
            ln_red_final_kernel<<<M, 256>>>(x, part, b2 + l*DD, lnfs, lnfb, out);
        }
    }
}

// round 17
// speedup vs baseline: 1.0088x; 1.0088x over previous
#include <cuda_runtime.h>
#include <cuda_fp16.h>
#include <cstdint>

#define BB 2
#define SS 1024
#define DD 1024
#define HH 16
#define DKK 64
#define FF_ 4096
#define LL 6

// ---------------- scratch (__device__ globals: allocation-free) --------------
__device__ float g_x [BB*SS*DD];
__device__ float g_p [2*BB*SS*DD];    // split-K partials (fp32, 16 MB)

#define WL_CHUNK (4*DD*DD + DD*FF_ + FF_*DD)
#define W_TOTAL  (LL * WL_CHUNK)
#define OFF_Q 0
#define OFF_K (DD*DD)
#define OFF_V (2*DD*DD)
#define OFF_O (3*DD*DD)
#define OFF_1 (4*DD*DD)
#define OFF_2 (4*DD*DD + DD*FF_)
__device__ __half g_w [W_TOTAL];

__device__ __half g_a [BB*SS*DD];
__device__ __half g_f [BB*SS*FF_];
__device__ __half g_q [BB*SS*DD];
__device__ __half g_k [BB*SS*DD];
__device__ __half g_v [BB*SS*DD];

// ---------------- PTX helpers -------------------------------------------------
__device__ __forceinline__ uint32_t smem_u32(const void* p) {
    uint32_t a;
    asm("{ .reg .u64 t; cvta.to.shared.u64 t, %1; cvt.u32.u64 %0, t; }" : "=r"(a) : "l"(p));
    return a;
}
#define CP16(d, s) asm volatile("cp.async.cg.shared.global [%0], [%1], 16;" :: "r"(d), "l"(s))
#define CP_COMMIT() asm volatile("cp.async.commit_group;" ::: "memory")

#define LDSM4(r, addr) \
    asm volatile("ldmatrix.sync.aligned.m8n8.x4.shared.b16 {%0,%1,%2,%3}, [%4];" \
        : "=r"((r)[0]), "=r"((r)[1]), "=r"((r)[2]), "=r"((r)[3]) : "r"(addr))
#define LDSM4T(r, addr) \
    asm volatile("ldmatrix.sync.aligned.m8n8.x4.trans.shared.b16 {%0,%1,%2,%3}, [%4];" \
        : "=r"((r)[0]), "=r"((r)[1]), "=r"((r)[2]), "=r"((r)[3]) : "r"(addr))

#define MMAF16(d, a, b) \
    asm volatile("mma.sync.aligned.m16n8k16.row.col.f32.f16.f16.f32 " \
        "{%0,%1,%2,%3}, {%4,%5,%6,%7}, {%8,%9}, {%0,%1,%2,%3};" \
        : "+f"((d)[0]), "+f"((d)[1]), "+f"((d)[2]), "+f"((d)[3]) \
        : "r"((a)[0]), "r"((a)[1]), "r"((a)[2]), "r"((a)[3]), "r"((b)[0]), "r"((b)[1]))

__device__ __forceinline__ uint32_t h2pack(float a, float b) {
    __half2 h = __floats2half2_rn(a, b);
    return *(uint32_t*)&h;
}
__device__ __forceinline__ float warpReduceSum(float v) {
#pragma unroll
    for (int o = 16; o; o >>= 1) v += __shfl_xor_sync(0xffffffffu, v, o);
    return v;
}

// ---------------- embed --------------------------------------------------------
__global__ void __launch_bounds__(256) embed_kernel(
    const int* __restrict__ ids, const float* __restrict__ emb,
    const float* __restrict__ pe, float* __restrict__ x)
{
    int row = blockIdx.x;
    int col = threadIdx.x * 4;
    int id  = ids[row];
    int s   = row & (SS - 1);
    float4 e = *(const float4*)&emb[(size_t)id * DD + col];
    float4 p = *(const float4*)&pe [(size_t)s  * DD + col];
    float4 o;
    o.x = e.x * 32.0f + p.x;
    o.y = e.y * 32.0f + p.y;
    o.z = e.z * 32.0f + p.z;
    o.w = e.w * 32.0f + p.w;
    *(float4*)&x[(size_t)row * DD + col] = o;
}

// ---------------- warp-per-row LayerNorm: fp16 out (layer-0 LN1) -----------------
__global__ void __launch_bounds__(256) ln_h_kernel(
    const float* __restrict__ x, const float* __restrict__ g,
    const float* __restrict__ b, __half* __restrict__ oh)
{
    int warp = threadIdx.x >> 5, lane = threadIdx.x & 31;
    int row = blockIdx.x * 8 + warp;
    const float4* xr = (const float4*)(x + (size_t)row * DD);
    float4 v[8];
    float s = 0.f;
#pragma unroll
    for (int i = 0; i < 8; i++) {
        v[i] = xr[lane + i * 32];
        s += v[i].x + v[i].y + v[i].z + v[i].w;
    }
    float mean = warpReduceSum(s) * (1.0f / DD);
    float vs = 0.f;
#pragma unroll
    for (int i = 0; i < 8; i++) {
        float dx = v[i].x - mean, dy = v[i].y - mean;
        float dz = v[i].z - mean, dw = v[i].w - mean;
        vs += dx*dx + dy*dy + dz*dz + dw*dw;
    }
    float rstd = rsqrtf(warpReduceSum(vs) * (1.0f / DD) + 1e-6f);
    uint2* ohr = (uint2*)(oh + (size_t)row * DD);
#pragma unroll
    for (int i = 0; i < 8; i++) {
        int col = (lane + i * 32) * 4;
        float4 gg = *(const float4*)&g[col];
        float4 bb = *(const float4*)&b[col];
        float ox = (v[i].x - mean) * rstd * gg.x + bb.x;
        float oy = (v[i].y - mean) * rstd * gg.y + bb.y;
        float oz = (v[i].z - mean) * rstd * gg.z + bb.z;
        float ow = (v[i].w - mean) * rstd * gg.w + bb.w;
        ohr[lane + i * 32] = make_uint2(h2pack(ox, oy), h2pack(oz, ow));
    }
}

// ---------------- warp-per-row fused: x += p0+p1+bias; LN(x) -> fp16 oh ----------
__global__ void __launch_bounds__(256) ln_h_red_kernel(
    float* __restrict__ x, const float* __restrict__ p,
    const float* __restrict__ bias,
    const float* __restrict__ g, const float* __restrict__ b,
    __half* __restrict__ oh)
{
    int warp = threadIdx.x >> 5, lane = threadIdx.x & 31;
    int row = blockIdx.x * 8 + warp;
    float4* xr = (float4*)(x + (size_t)row * DD);
    const float4* p0r = (const float4*)(p + (size_t)row * DD);
    const float4* p1r = (const float4*)(p + (size_t)row * DD + (size_t)BB*SS*DD);
    const float4* br  = (const float4*)bias;
    float4 v[8];
    float s = 0.f;
#pragma unroll
    for (int i = 0; i < 8; i++) {
        int idx = lane + i * 32;
        float4 a0 = xr[idx];
        float4 q0 = p0r[idx];
        float4 q1 = p1r[idx];
        float4 bi = br[idx];
        a0.x += q0.x + q1.x + bi.x;
        a0.y += q0.y + q1.y + bi.y;
        a0.z += q0.z + q1.z + bi.z;
        a0.w += q0.w + q1.w + bi.w;
        xr[idx] = a0;
        v[i] = a0;
        s += a0.x + a0.y + a0.z + a0.w;
    }
    float mean = warpReduceSum(s) * (1.0f / DD);
    float vs = 0.f;
#pragma unroll
    for (int i = 0; i < 8; i++) {
        float dx = v[i].x - mean, dy = v[i].y - mean;
        float dz = v[i].z - mean, dw = v[i].w - mean;
        vs += dx*dx + dy*dy + dz*dz + dw*dw;
    }
    float rstd = rsqrtf(warpReduceSum(vs) * (1.0f / DD) + 1e-6f);
    uint2* ohr = (uint2*)(oh + (size_t)row * DD);
#pragma unroll
    for (int i = 0; i < 8; i++) {
        int col = (lane + i * 32) * 4;
        float4 gg = *(const float4*)&g[col];
        float4 bb = *(const float4*)&b[col];
        float ox = (v[i].x - mean) * rstd * gg.x + bb.x;
        float oy = (v[i].y - mean) * rstd * gg.y + bb.y;
        float oz = (v[i].z - mean) * rstd * gg.z + bb.z;
        float ow = (v[i].w - mean) * rstd * gg.w + bb.w;
        ohr[lane + i * 32] = make_uint2(h2pack(ox, oy), h2pack(oz, ow));
    }
}

// ---------------- warp-per-row final: xn = x+p0+p1+bias; LN(xn) -> fp32 out ------
__global__ void __launch_bounds__(256) ln_red_final_kernel(
    const float* __restrict__ x, const float* __restrict__ p,
    const float* __restrict__ bias,
    const float* __restrict__ g, const float* __restrict__ b,
    float* __restrict__ out)
{
    int warp = threadIdx.x >> 5, lane = threadIdx.x & 31;
    int row = blockIdx.x * 8 + warp;
    const float4* xr  = (const float4*)(x + (size_t)row * DD);
    const float4* p0r = (const float4*)(p + (size_t)row * DD);
    const float4* p1r = (const float4*)(p + (size_t)row * DD + (size_t)BB*SS*DD);
    const float4* br  = (const float4*)bias;
    float4 v[8];
    float s = 0.f;
#pragma unroll
    for (int i = 0; i < 8; i++) {
        int idx = lane + i * 32;
        float4 a0 = xr[idx];
        float4 q0 = p0r[idx];
        float4 q1 = p1r[idx];
        float4 bi = br[idx];
        a0.x += q0.x + q1.x + bi.x;
        a0.y += q0.y + q1.y + bi.y;
        a0.z += q0.z + q1.z + bi.z;
        a0.w += q0.w + q1.w + bi.w;
        v[i] = a0;
        s += a0.x + a0.y + a0.z + a0.w;
    }
    float mean = warpReduceSum(s) * (1.0f / DD);
    float vs = 0.f;
#pragma unroll
    for (int i = 0; i < 8; i++) {
        float dx = v[i].x - mean, dy = v[i].y - mean;
        float dz = v[i].z - mean, dw = v[i].w - mean;
        vs += dx*dx + dy*dy + dz*dz + dw*dw;
    }
    float rstd = rsqrtf(warpReduceSum(vs) * (1.0f / DD) + 1e-6f);
    float4* outr = (float4*)(out + (size_t)row * DD);
#pragma unroll
    for (int i = 0; i < 8; i++) {
        int col = (lane + i * 32) * 4;
        float4 gg = *(const float4*)&g[col];
        float4 bb = *(const float4*)&b[col];
        float4 o;
        o.x = (v[i].x - mean) * rstd * gg.x + bb.x;
        o.y = (v[i].y - mean) * rstd * gg.y + bb.y;
        o.z = (v[i].z - mean) * rstd * gg.z + bb.z;
        o.w = (v[i].w - mean) * rstd * gg.w + bb.w;
        outr[lane + i * 32] = o;
    }
}

// ---------------- batched weight prep (fp32 [K,N] -> fp16 [N,K]) ------------------
__global__ void __launch_bounds__(256) prep_qkvo(
    const float* __restrict__ wq, const float* __restrict__ wk,
    const float* __restrict__ wv, const float* __restrict__ wo,
    __half* __restrict__ dh)
{
    __shared__ float tile[32][33];
    int z = blockIdx.z, l = z >> 2, ws = z & 3;
    const float* src = (ws == 0 ? wq : ws == 1 ? wk : ws == 2 ? wv : wo) + (size_t)l * DD * DD;
    size_t dbase = (size_t)l * WL_CHUNK + (size_t)ws * DD * DD;
    int k0 = blockIdx.y * 32, n0 = blockIdx.x * 32;
    int tx = threadIdx.x & 31, ty = threadIdx.x >> 5;
#pragma unroll
    for (int i = ty; i < 32; i += 8)
        tile[i][tx] = src[(size_t)(k0 + i) * DD + n0 + tx];
    __syncthreads();
#pragma unroll
    for (int i = ty; i < 32; i += 8)
        dh[dbase + (size_t)(n0 + i) * DD + k0 + tx] = __float2half_rn(tile[tx][i]);
}

__global__ void __launch_bounds__(256) prep_ff(
    const float* __restrict__ src, __half* __restrict__ dh,
    int dstOff, int K, int N)
{
    __shared__ float tile[32][33];
    int l = blockIdx.z;
    const float* s = src + (size_t)l * K * N;
    size_t dbase = (size_t)l * WL_CHUNK + dstOff;
    int k0 = blockIdx.y * 32, n0 = blockIdx.x * 32;
    int tx = threadIdx.x & 31, ty = threadIdx.x >> 5;
#pragma unroll
    for (int i = ty; i < 32; i += 8)
        tile[i][tx] = s[(size_t)(k0 + i) * N + n0 + tx];
    __syncthreads();
#pragma unroll
    for (int i = ty; i < 32; i += 8)
        dh[dbase + (size_t)(n0 + i) * K + k0 + tx] = __float2half_rn(tile[tx][i]);
}

// ================================================================================
// fp16 GEMM (R8 config): 256 thr, 128x128 tile, 32x64 warp tiles, 2 CTAs/SM.
// EP: 4 = fp16 out, 5 = relu(+bias) fp16 out.
// ================================================================================
struct BPtr { const __half* h; float* c; __half* ch; };

#define STAGE_BYTES 36864
#define MM_SMEM (2 * STAGE_BYTES)

template<int EP>
__global__ void __launch_bounds__(256, 2) mmagemm(
    const __half* __restrict__ Ah,
    BPtr p0, BPtr p1, BPtr p2,
    const float* __restrict__ bias, const float* __restrict__ Rs,
    int M, int N, int K)
{
    extern __shared__ char smem[];
    uint32_t sb = smem_u32(smem);
    int z = blockIdx.z;
    BPtr P = (z == 0) ? p0 : (z == 1 ? p1 : p2);
    const __half* Bh = P.h;

    int tid = threadIdx.x;
    int bm = blockIdx.y * 128, bn = blockIdx.x * 128;

    const __half* Ab = Ah + (size_t)bm * K;
    const __half* Bb = Bh + (size_t)bn * K;

    auto load_stage = [&](int s, int k0) {
        uint32_t st = sb + (uint32_t)s * STAGE_BYTES;
#pragma unroll
        for (int i = 0; i < 4; i++) {
            int id = i * 256 + tid;
            int r = id >> 3, c = id & 7;
            uint32_t so = (uint32_t)(r * 144 + c * 16);
            size_t go = (size_t)r * K + k0 + c * 8;
            CP16(st +         so, (const char*)(Ab + go));
            CP16(st + 18432 + so, (const char*)(Bb + go));
        }
    };

    int wid = tid >> 5, lane = tid & 31;
    int wm = (wid & 3) * 32;
    int wn = (wid >> 2) * 64;
    int lrow  = lane & 15;
    int lcol8 = (lane >> 4) * 8;

    float acc[2][8][4];
#pragma unroll
    for (int a = 0; a < 2; a++)
#pragma unroll
        for (int b = 0; b < 8; b++)
#pragma unroll
            for (int cth = 0; cth < 4; cth++) acc[a][b][cth] = 0.f;

    int NT = K >> 6;
    load_stage(0, 0);
    CP_COMMIT();

    for (int t = 0; t < NT; t++) {
        if (t + 1 < NT) {
            load_stage((t + 1) & 1, (t + 1) * 64);
            CP_COMMIT();
            asm volatile("cp.async.wait_group 1;" ::: "memory");
        } else {
            asm volatile("cp.async.wait_group 0;" ::: "memory");
        }
        __syncthreads();

        uint32_t sA = sb + (uint32_t)(t & 1) * STAGE_BYTES;
        uint32_t sB = sA + 18432;
#pragma unroll
        for (int ks = 0; ks < 4; ks++) {
            int k0 = ks * 16;
            uint32_t ah[2][4];
#pragma unroll
            for (int mf = 0; mf < 2; mf++) {
                uint32_t ad = sA + (uint32_t)((wm + mf * 16 + lrow) * 144 + (k0 + lcol8) * 2);
                LDSM4(ah[mf], ad);
            }
#pragma unroll
            for (int nf2 = 0; nf2 < 4; nf2++) {
                uint32_t ad = sB + (uint32_t)((wn + nf2 * 16 + lrow) * 144 + (k0 + lcol8) * 2);
                uint32_t tmp[4];
                LDSM4(tmp, ad);
                uint32_t b0[2] = { tmp[0], tmp[2] };
                uint32_t b1[2] = { tmp[1], tmp[3] };
#pragma unroll
                for (int mf = 0; mf < 2; mf++) {
                    MMAF16(acc[mf][nf2*2],   ah[mf], b0);
                    MMAF16(acc[mf][nf2*2+1], ah[mf], b1);
                }
            }
        }
        __syncthreads();
    }

#pragma unroll
    for (int mf = 0; mf < 2; mf++) {
        int r0 = bm + wm + mf * 16 + (lane >> 2);
#pragma unroll
        for (int nf = 0; nf < 8; nf++) {
            int col = bn + wn + nf * 8 + (lane & 3) * 2;
            float2 v0 = make_float2(acc[mf][nf][0], acc[mf][nf][1]);
            float2 v1 = make_float2(acc[mf][nf][2], acc[mf][nf][3]);
            if (EP == 5) {
                float2 bi = *(const float2*)&bias[col];
                v0.x = fmaxf(v0.x + bi.x, 0.f); v0.y = fmaxf(v0.y + bi.y, 0.f);
                v1.x = fmaxf(v1.x + bi.x, 0.f); v1.y = fmaxf(v1.y + bi.y, 0.f);
            }
            *(uint32_t*)&P.ch[(size_t)r0 * N + col]       = h2pack(v0.x, v0.y);
            *(uint32_t*)&P.ch[(size_t)(r0 + 8) * N + col] = h2pack(v1.x, v1.y);
        }
    }
}

// ================================================================================
// Split-K GEMM: fp32 partials, z = K-split index (K/2 each). (Wo and FF2)
// ================================================================================
__global__ void __launch_bounds__(256, 2) mmagemm_sk(
    const __half* __restrict__ Ah, const __half* __restrict__ Bh,
    float* __restrict__ Part, int M, int N, int K)
{
    extern __shared__ char smem[];
    uint32_t sb = smem_u32(smem);
    int z = blockIdx.z;
    int kOff = z * (K >> 1);
    int kLen = K >> 1;
    float* C = Part + (size_t)z * M * N;

    int tid = threadIdx.x;
    int bm = blockIdx.y * 128, bn = blockIdx.x * 128;

    const __half* Ab = Ah + (size_t)bm * K + kOff;
    const __half* Bb = Bh + (size_t)bn * K + kOff;

    auto load_stage = [&](int s, int k0) {
        uint32_t st = sb + (uint32_t)s * STAGE_BYTES;
#pragma unroll
        for (int i = 0; i < 4; i++) {
            int id = i * 256 + tid;
            int r = id >> 3, c = id & 7;
            uint32_t so = (uint32_t)(r * 144 + c * 16);
            size_t go = (size_t)r * K + k0 + c * 8;
            CP16(st +         so, (const char*)(Ab + go));
            CP16(st + 18432 + so, (const char*)(Bb + go));
        }
    };

    int wid = tid >> 5, lane = tid & 31;
    int wm = (wid & 3) * 32;
    int wn = (wid >> 2) * 64;
    int lrow  = lane & 15;
    int lcol8 = (lane >> 4) * 8;

    float acc[2][8][4];
#pragma unroll
    for (int a = 0; a < 2; a++)
#pragma unroll
        for (int b = 0; b < 8; b++)
#pragma unroll
            for (int cth = 0; cth < 4; cth++) acc[a][b][cth] = 0.f;

    int NT = kLen >> 6;
    load_stage(0, 0);
    CP_COMMIT();

    for (int t = 0; t < NT; t++) {
        if (t + 1 < NT) {
            load_stage((t + 1) & 1, (t + 1) * 64);
            CP_COMMIT();
            asm volatile("cp.async.wait_group 1;" ::: "memory");
        } else {
            asm volatile("cp.async.wait_group 0;" ::: "memory");
        }
        __syncthreads();

        uint32_t sA = sb + (uint32_t)(t & 1) * STAGE_BYTES;
        uint32_t sB = sA + 18432;
#pragma unroll
        for (int ks = 0; ks < 4; ks++) {
            int k0 = ks * 16;
            uint32_t ah[2][4];
#pragma unroll
            for (int mf = 0; mf < 2; mf++) {
                uint32_t ad = sA + (uint32_t)((wm + mf * 16 + lrow) * 144 + (k0 + lcol8) * 2);
                LDSM4(ah[mf], ad);
            }
#pragma unroll
            for (int nf2 = 0; nf2 < 4; nf2++) {
                uint32_t ad = sB + (uint32_t)((wn + nf2 * 16 + lrow) * 144 + (k0 + lcol8) * 2);
                uint32_t tmp[4];
                LDSM4(tmp, ad);
                uint32_t b0[2] = { tmp[0], tmp[2] };
                uint32_t b1[2] = { tmp[1], tmp[3] };
#pragma unroll
                for (int mf = 0; mf < 2; mf++) {
                    MMAF16(acc[mf][nf2*2],   ah[mf], b0);
                    MMAF16(acc[mf][nf2*2+1], ah[mf], b1);
                }
            }
        }
        __syncthreads();
    }

#pragma unroll
    for (int mf = 0; mf < 2; mf++) {
        int r0 = bm + wm + mf * 16 + (lane >> 2);
#pragma unroll
        for (int nf = 0; nf < 8; nf++) {
            int col = bn + wn + nf * 8 + (lane & 3) * 2;
            *(float2*)&C[(size_t)r0 * N + col]       = make_float2(acc[mf][nf][0], acc[mf][nf][1]);
            *(float2*)&C[(size_t)(r0 + 8) * N + col] = make_float2(acc[mf][nf][2], acc[mf][nf][3]);
        }
    }
}

// ================================================================================
// Flash attention: fp16 Q/K/V, fp32 accum, online softmax. 2 CTAs/SM. (unchanged)
// ================================================================================
#define FA_STRIDE 144
#define FA_Q 0
#define FA_KV0 18432
#define FA_KVSTAGE 36864
#define FA_MB 92160
#define FA_SMEM 93184

__global__ void __launch_bounds__(256, 2) flash_kernel(
    const __half* __restrict__ q, const __half* __restrict__ k,
    const __half* __restrict__ v,
    const float* __restrict__ am,
    __half* __restrict__ o)
{
    extern __shared__ char smem[];
    uint32_t sb = smem_u32(smem);
    float* maskf = (float*)(smem + FA_MB);

    int qt = blockIdx.x;
    int bh = blockIdx.y;
    int b  = bh >> 4, hd = bh & 15;
    int tid = threadIdx.x;
    int wid = tid >> 5, lane = tid & 31;
    int wm = wid * 16;
    int lrow  = lane & 15;
    int lcol8 = (lane >> 4) * 8;

    size_t qrow0 = (size_t)b * SS + qt * 128;
    size_t hoff  = (size_t)hd * DKK;

#pragma unroll
    for (int i = 0; i < 4; i++) {
        int id = i * 256 + tid;
        int r = id >> 3, c = id & 7;
        uint32_t so = (uint32_t)(r * FA_STRIDE + c * 16);
        size_t gq = (qrow0 + r) * DD + hoff + c * 8;
        CP16(sb + FA_Q + so, (const char*)(q + gq));
        size_t gk = ((size_t)b * SS + r) * DD + hoff + c * 8;
        CP16(sb + FA_KV0 +         so, (const char*)(k + gk));
        CP16(sb + FA_KV0 + 18432 + so, (const char*)(v + gk));
    }
    CP_COMMIT();
    if (tid < 128) {
        float m = am[(size_t)b * SS + tid];
        maskf[tid] = (m == 0.f) ? -1e9f : 0.f;
    }

    float m0 = -1e30f, m1 = -1e30f, s0 = 0.f, s1 = 0.f;
    float oacc[8][4];
#pragma unroll
    for (int i = 0; i < 8; i++)
#pragma unroll
        for (int j = 0; j < 4; j++) oacc[i][j] = 0.f;

    for (int t = 0; t < 8; t++) {
        asm volatile("cp.async.wait_group 0;" ::: "memory");
        __syncthreads();

        if (t + 1 < 8) {
            uint32_t kvn = sb + FA_KV0 + (uint32_t)((t + 1) & 1) * FA_KVSTAGE;
#pragma unroll
            for (int i = 0; i < 4; i++) {
                int id = i * 256 + tid;
                int r = id >> 3, c = id & 7;
                uint32_t so = (uint32_t)(r * FA_STRIDE + c * 16);
                size_t go = ((size_t)b * SS + (t + 1) * 128 + r) * DD + hoff + c * 8;
                CP16(kvn +         so, (const char*)(k + go));
                CP16(kvn + 18432 + so, (const char*)(v + go));
            }
            CP_COMMIT();
            if (tid < 128) {
                float m = am[(size_t)b * SS + (t + 1) * 128 + tid];
                maskf[((t + 1) & 1) * 128 + tid] = (m == 0.f) ? -1e9f : 0.f;
            }
        }

        uint32_t kvb = sb + FA_KV0 + (uint32_t)(t & 1) * FA_KVSTAGE;
        const float* mk = maskf + (t & 1) * 128;

        float sacc[16][4];
#pragma unroll
        for (int i = 0; i < 16; i++)
#pragma unroll
            for (int j = 0; j < 4; j++) sacc[i][j] = 0.f;

#pragma unroll
        for (int kf = 0; kf < 4; kf++) {
            uint32_t aq[4];
            uint32_t ad = sb + FA_Q + (uint32_t)((wm + lrow) * FA_STRIDE + (kf * 16 + lcol8) * 2);
            LDSM4(aq, ad);
#pragma unroll
            for (int nf2 = 0; nf2 < 8; nf2++) {
                uint32_t kd = kvb + (uint32_t)((nf2 * 16 + lrow) * FA_STRIDE + (kf * 16 + lcol8) * 2);
                uint32_t tmp[4];
                LDSM4(tmp, kd);
                uint32_t b0[2] = { tmp[0], tmp[2] };
                uint32_t b1[2] = { tmp[1], tmp[3] };
                MMAF16(sacc[nf2*2],   aq, b0);
                MMAF16(sacc[nf2*2+1], aq, b1);
            }
        }

        float mn0 = m0, mn1 = m1;
#pragma unroll
        for (int nf = 0; nf < 16; nf++) {
            int col = nf * 8 + (lane & 3) * 2;
            float b0 = mk[col], b1 = mk[col + 1];
            sacc[nf][0] = sacc[nf][0] * 0.125f + b0;
            sacc[nf][1] = sacc[nf][1] * 0.125f + b1;
            sacc[nf][2] = sacc[nf][2] * 0.125f + b0;
            sacc[nf][3] = sacc[nf][3] * 0.125f + b1;
            mn0 = fmaxf(mn0, fmaxf(sacc[nf][0], sacc[nf][1]));
            mn1 = fmaxf(mn1, fmaxf(sacc[nf][2], sacc[nf][3]));
        }
        mn0 = fmaxf(mn0, __shfl_xor_sync(0xffffffffu, mn0, 1));
        mn0 = fmaxf(mn0, __shfl_xor_sync(0xffffffffu, mn0, 2));
        mn1 = fmaxf(mn1, __shfl_xor_sync(0xffffffffu, mn1, 1));
        mn1 = fmaxf(mn1, __shfl_xor_sync(0xffffffffu, mn1, 2));
        float alpha0 = __expf(m0 - mn0);
        float alpha1 = __expf(m1 - mn1);
        m0 = mn0; m1 = mn1;
        float rs0 = 0.f, rs1 = 0.f;
#pragma unroll
        for (int nf = 0; nf < 16; nf++) {
            sacc[nf][0] = __expf(sacc[nf][0] - mn0);
            sacc[nf][1] = __expf(sacc[nf][1] - mn0);
            sacc[nf][2] = __expf(sacc[nf][2] - mn1);
            sacc[nf][3] = __expf(sacc[nf][3] - mn1);
            rs0 += sacc[nf][0] + sacc[nf][1];
            rs1 += sacc[nf][2] + sacc[nf][3];
        }
        rs0 += __shfl_xor_sync(0xffffffffu, rs0, 1);
        rs0 += __shfl_xor_sync(0xffffffffu, rs0, 2);
        rs1 += __shfl_xor_sync(0xffffffffu, rs1, 1);
        rs1 += __shfl_xor_sync(0xffffffffu, rs1, 2);
        s0 = s0 * alpha0 + rs0;
        s1 = s1 * alpha1 + rs1;
#pragma unroll
        for (int i = 0; i < 8; i++) {
            oacc[i][0] *= alpha0; oacc[i][1] *= alpha0;
            oacc[i][2] *= alpha1; oacc[i][3] *= alpha1;
        }

#pragma unroll
        for (int kk = 0; kk < 8; kk++) {
            uint32_t ap[4];
            ap[0] = h2pack(sacc[2*kk][0],   sacc[2*kk][1]);
            ap[1] = h2pack(sacc[2*kk][2],   sacc[2*kk][3]);
            ap[2] = h2pack(sacc[2*kk+1][0], sacc[2*kk+1][1]);
            ap[3] = h2pack(sacc[2*kk+1][2], sacc[2*kk+1][3]);
#pragma unroll
            for (int dv2 = 0; dv2 < 4; dv2++) {
                uint32_t tmp[4];
                uint32_t vd = kvb + 18432 + (uint32_t)((kk * 16 + lrow) * FA_STRIDE + (dv2 * 16 + lcol8) * 2);
                LDSM4T(tmp, vd);
                uint32_t bv0[2] = { tmp[0], tmp[1] };
                uint32_t bv1[2] = { tmp[2], tmp[3] };
                MMAF16(oacc[dv2*2],   ap, bv0);
                MMAF16(oacc[dv2*2+1], ap, bv1);
            }
        }
    }

    float inv0 = 1.0f / s0, inv1 = 1.0f / s1;
    int r0 = (int)qrow0 + wm + (lane >> 2);
#pragma unroll
    for (int nf = 0; nf < 8; nf++) {
        int col = (int)hoff + nf * 8 + (lane & 3) * 2;
        *(uint32_t*)&o[(size_t)r0 * DD + col]       = h2pack(oacc[nf][0] * inv0, oacc[nf][1] * inv0);
        *(uint32_t*)&o[(size_t)(r0 + 8) * DD + col] = h2pack(oacc[nf][2] * inv1, oacc[nf][3] * inv1);
    }
}

// ---------------- host orchestration ---------------------------------------------
extern "C" void kernel_launch(void* const* d_in, const int* in_sizes, int n_in,
                              void* d_out, int out_size)
{
    const int*   ids  = (const int*)  d_in[0];
    const float* am   = (const float*)d_in[1];
    const float* emb  = (const float*)d_in[2];
    const float* pe   = (const float*)d_in[3];
    const float* wq   = (const float*)d_in[4];
    const float* wk   = (const float*)d_in[5];
    const float* wv   = (const float*)d_in[6];
    const float* wo   = (const float*)d_in[7];
    const float* bo   = (const float*)d_in[8];
    const float* w1   = (const float*)d_in[9];
    const float* b1   = (const float*)d_in[10];
    const float* w2   = (const float*)d_in[11];
    const float* b2   = (const float*)d_in[12];
    const float* ln1s = (const float*)d_in[13];
    const float* ln1b = (const float*)d_in[14];
    const float* ln2s = (const float*)d_in[15];
    const float* ln2b = (const float*)d_in[16];
    const float* lnfs = (const float*)d_in[17];
    const float* lnfb = (const float*)d_in[18];
    float* out = (float*)d_out;

    float *x, *part;
    __half *w, *a, *f, *q_, *k_, *v_;
    cudaGetSymbolAddress((void**)&x,    g_x);
    cudaGetSymbolAddress((void**)&part, g_p);
    cudaGetSymbolAddress((void**)&w,    g_w);
    cudaGetSymbolAddress((void**)&a,    g_a);
    cudaGetSymbolAddress((void**)&f,    g_f);
    cudaGetSymbolAddress((void**)&q_,   g_q);
    cudaGetSymbolAddress((void**)&k_,   g_k);
    cudaGetSymbolAddress((void**)&v_,   g_v);

    cudaFuncSetAttribute((const void*)mmagemm<4>, cudaFuncAttributeMaxDynamicSharedMemorySize, MM_SMEM);
    cudaFuncSetAttribute((const void*)mmagemm<5>, cudaFuncAttributeMaxDynamicSharedMemorySize, MM_SMEM);
    cudaFuncSetAttribute((const void*)mmagemm_sk, cudaFuncAttributeMaxDynamicSharedMemorySize, MM_SMEM);
    cudaFuncSetAttribute((const void*)flash_kernel, cudaFuncAttributeMaxDynamicSharedMemorySize, FA_SMEM);

    const int M = BB * SS;

    embed_kernel<<<M, 256>>>(ids, emb, pe, x);
    prep_qkvo<<<dim3(DD/32, DD/32, 4*LL), 256>>>(wq, wk, wv, wo, w);

    // layer-0 LN1 (x from embed) -- warp-per-row
    ln_h_kernel<<<M/8, 256>>>(x, ln1s, ln1b, a);

    for (int l = 0; l < LL; l++) {
        size_t lb = (size_t)l * WL_CHUNK;

        // fused Q,K,V projections (a = LN1 out)
        BPtr pq = { w + lb + OFF_Q, nullptr, q_ };
        BPtr pk = { w + lb + OFF_K, nullptr, k_ };
        BPtr pv = { w + lb + OFF_V, nullptr, v_ };
        mmagemm<4><<<dim3(DD/128, M/128, 3), 256, MM_SMEM>>>(a, pq, pk, pv,
                                                             nullptr, nullptr, M, DD, DD);

        if (l == 0) {
            prep_ff<<<dim3(FF_/32, DD/32, LL), 256>>>(w1, w, OFF_1, DD, FF_);
            prep_ff<<<dim3(DD/32, FF_/32, LL), 256>>>(w2, w, OFF_2, FF_, DD);
        }

        // flash attention -> fp16 attn out in a
        flash_kernel<<<dim3(SS/128, BB*HH), 256, FA_SMEM>>>(q_, k_, v_, am, a);

        // Wo: split-K=2 -> fp32 partials; fused warp-per-row reduce+LN2 -> a
        mmagemm_sk<<<dim3(DD/128, M/128, 2), 256, MM_SMEM>>>(a, w + lb + OFF_O, part,
                                                             M, DD, DD);
        ln_h_red_kernel<<<M/8, 256>>>(x, part, bo + l*DD, ln2s + l*DD, ln2b + l*DD, a);

        // ff = relu(a @ W1 + b1) -> f
        BPtr p1 = { w + lb + OFF_1, nullptr, f };
        mmagemm<5><<<dim3(FF_/128, M/128, 1), 256, MM_SMEM>>>(a, p1, p1, p1,
                                                              b1 + l*FF_, nullptr, M, FF_, DD);

        // FF2: split-K=2 -> fp32 partials; fused reduce + (next LN1 | final LN)
        mmagemm_sk<<<dim3(DD/128, M/128, 2), 256, MM_SMEM>>>(f, w + lb + OFF_2, part,
                                                             M, DD, FF_);
        if (l + 1 < LL) {
            ln_h_red_kernel<<<M/8, 256>>>(x, part, b2 + l*DD,
                                          ln1s + (l+1)*DD, ln1b + (l+1)*DD, a);
        } else {
            ln_red_final_kernel<<<M/8, 256>>>(x, part, b2 + l*DD, lnfs, lnfb, out);
        }
    }
}